// round 7
// baseline (speedup 1.0000x reference)
#include <cuda_runtime.h>

#define NPTS 2000000
#define NG   16384

typedef unsigned long long u64;

// Scratch (device globals: allocation-free, graph-capturable)
__device__ float g_xe[NPTS * 5];        // per-point embedding
__device__ float g_aggr[NG * 5];        // segment sum of xe
__device__ float g_pooled[NG * 32];     // segment sum of xo
__device__ u64   g_hbias[NG * 20];      // per-graph W1b·xg, packed pairs
__device__ u64   g_We2t_dev[100];       // prep: We2 transposed packed
__device__ u64   g_Wo2t_dev[640];       // prep: Wo2 transposed packed

// Weights in constant memory (uniform-const port, off the L1 path)
__constant__ u64 cWe1[60];     // [3][40] packed over outputs
__constant__ u64 cWe2t[100];   // transposed: [5 outputs][20 hidden-pairs]
__constant__ u64 cWg1[100];    // [5][40]
__constant__ u64 cWg2[80];     // [40][4]
__constant__ u64 cWo1[180];    // [9][40]: rows 0-4 used by k_out, rows 5-8 by k_glob
__constant__ u64 cWo2t[640];   // transposed: [32 outputs][20 hidden-pairs]
__constant__ u64 cWd1[640];    // [32][40]
__constant__ u64 cWd2[20];     // [40][1]

// ---------- packed f32x2 helpers ----------
__device__ __forceinline__ u64 pk2(float lo, float hi) {
    u64 r; asm("mov.b64 %0, {%1, %2};" : "=l"(r) : "f"(lo), "f"(hi)); return r;
}
__device__ __forceinline__ void up2(u64 v, float& lo, float& hi) {
    asm("mov.b64 {%0, %1}, %2;" : "=f"(lo), "=f"(hi) : "l"(v));
}
__device__ __forceinline__ u64 ffma2(u64 a, u64 b, u64 c) {
    u64 d; asm("fma.rn.f32x2 %0, %1, %2, %3;" : "=l"(d) : "l"(a), "l"(b), "l"(c)); return d;
}
__device__ __forceinline__ u64 mul2(u64 a, u64 b) {
    u64 d; asm("mul.rn.f32x2 %0, %1, %2;" : "=l"(d) : "l"(a), "l"(b)); return d;
}
__device__ __forceinline__ u64 add2(u64 a, u64 b) {
    u64 d; asm("add.rn.f32x2 %0, %1, %2;" : "=l"(d) : "l"(a), "l"(b)); return d;
}
// scalar leaky_relu (exact)
__device__ __forceinline__ float lrelu(float v) { return fmaxf(v, 0.01f * v); }
// packed leaky_relu: 0.505x + 0.495|x| (== lrelu to ~6e-6 rel, no unpack)
__device__ __forceinline__ u64 plrelu2(u64 v) {
    u64 cA = pk2(0.505f, 0.505f), cB = pk2(0.495f, 0.495f);
    u64 av = v & 0x7FFFFFFF7FFFFFFFULL;
    return ffma2(av, cB, mul2(v, cA));
}

// ---------- pre: zero g_aggr + build transposed packed layer-2 weights ----------
__global__ void __launch_bounds__(256) k_pre(const float* __restrict__ We2,   // [40][5]
                                             const float* __restrict__ Wo2) { // [40][32]
    int i = blockIdx.x * 256 + threadIdx.x;
    if (i < NG * 5 / 4) ((float4*)g_aggr)[i] = make_float4(0.f, 0.f, 0.f, 0.f);
    if (i < 100) {
        int j = i / 20, q = i % 20;
        g_We2t_dev[i] = pk2(We2[(2 * q) * 5 + j], We2[(2 * q + 1) * 5 + j]);
    }
    if (i < 640) {
        int j = i / 20, q = i % 20;
        g_Wo2t_dev[i] = pk2(Wo2[(2 * q) * 32 + j], Wo2[(2 * q + 1) * 32 + j]);
    }
}

// =====================================================================
// Pass 1: xe = ffn(x, We1, We2); store xe; segment-sum -> g_aggr.  P=2.
// =====================================================================
__global__ void __launch_bounds__(256, 2) k_emb(const float* __restrict__ x,
                                                const int* __restrict__ batch) {
    int tid = threadIdx.x;
    int t = blockIdx.x * 256 + tid;
    int i0 = t * 2;
    if (i0 >= NPTS) return;   // NPTS % 64 == 0 -> surviving warps are full

    const float2* xp = (const float2*)(x + i0 * 3);
    float2 p0 = xp[0], p1 = xp[1], p2 = xp[2];
    float inA[3] = {p0.x, p0.y, p1.x};
    float inB[3] = {p1.y, p2.x, p2.y};

    // hidden 3 -> 40 (packed over outputs)
    u64 hA[20], hB[20];
#pragma unroll
    for (int q = 0; q < 20; q++) { hA[q] = 0ULL; hB[q] = 0ULL; }
#pragma unroll
    for (int k = 0; k < 3; k++) {
        u64 aA = pk2(inA[k], inA[k]);
        u64 aB = pk2(inB[k], inB[k]);
#pragma unroll
        for (int q = 0; q < 20; q++) {
            u64 w = cWe1[k * 20 + q];
            hA[q] = ffma2(aA, w, hA[q]);
            hB[q] = ffma2(aB, w, hB[q]);
        }
    }
#pragma unroll
    for (int q = 0; q < 20; q++) { hA[q] = plrelu2(hA[q]); hB[q] = plrelu2(hB[q]); }

    // out 40 -> 5: packed dot over hidden pairs (transposed weights)
    float xeA[5], xeB[5];
#pragma unroll
    for (int j = 0; j < 5; j++) {
        u64 aA = 0ULL, aB = 0ULL;
#pragma unroll
        for (int q = 0; q < 20; q++) {
            u64 w = cWe2t[j * 20 + q];
            aA = ffma2(hA[q], w, aA);
            aB = ffma2(hB[q], w, aB);
        }
        float lo, hi;
        up2(aA, lo, hi); xeA[j] = lrelu(lo + hi);
        up2(aB, lo, hi); xeB[j] = lrelu(lo + hi);
    }

    // store xe for both points: 10 consecutive floats -> 5 STG.64
    {
        float2* xo = (float2*)(g_xe + i0 * 5);
        xo[0] = make_float2(xeA[0], xeA[1]);
        xo[1] = make_float2(xeA[2], xeA[3]);
        xo[2] = make_float2(xeA[4], xeB[0]);
        xo[3] = make_float2(xeB[1], xeB[2]);
        xo[4] = make_float2(xeB[3], xeB[4]);
    }

    // segmented sum -> g_aggr
    int2 bb = *(const int2*)(batch + i0);
    int bA = bb.x, bB = bb.y;
    bool same = (bA == bB);
    unsigned peers = __match_any_sync(0xffffffffu, bA);
    int lane = tid & 31;
    int hiL = 31 - __clz(peers);
    bool leader = (lane == __ffs(peers) - 1);
#pragma unroll
    for (int c = 0; c < 5; c++) {
        float v = same ? (xeA[c] + xeB[c]) : xeA[c];
#pragma unroll
        for (int d = 1; d < 32; d <<= 1) {
            float s = __shfl_down_sync(0xffffffffu, v, d);
            if (lane + d <= hiL) v += s;
        }
        if (leader) atomicAdd(&g_aggr[bA * 5 + c], v);
        if (!same)  atomicAdd(&g_aggr[bB * 5 + c], xeB[c]);  // rare boundary leftover
    }
}

// =====================================================================
// Pass 2: xg = ffn(x_aggr, Wg1, Wg2); hbias = W1b·xg (packed) -> g_hbias.
// Also zeroes g_pooled.
// =====================================================================
__global__ void __launch_bounds__(256) k_glob() {
    int g = blockIdx.x * 256 + threadIdx.x;   // grid = NG/256 exactly

    {   // zero g_pooled: 128K float4 over 16384 threads -> 8 each
        float4 z = make_float4(0.f, 0.f, 0.f, 0.f);
        float4* pp = (float4*)g_pooled;
#pragma unroll
        for (int r = 0; r < 8; r++) pp[g * 8 + r] = z;
    }

    float in5[5];
#pragma unroll
    for (int j = 0; j < 5; j++) in5[j] = g_aggr[g * 5 + j];

    u64 acc[20];
#pragma unroll
    for (int j = 0; j < 20; j++) acc[j] = 0ULL;
#pragma unroll
    for (int k = 0; k < 5; k++) {
        u64 a = pk2(in5[k], in5[k]);
#pragma unroll
        for (int q = 0; q < 20; q++) acc[q] = ffma2(a, cWg1[k * 20 + q], acc[q]);
    }
    float hf[40];
#pragma unroll
    for (int j = 0; j < 20; j++) {
        float lo, hi; up2(acc[j], lo, hi);
        hf[2 * j] = lrelu(lo); hf[2 * j + 1] = lrelu(hi);
    }
    u64 o01 = 0ULL, o23 = 0ULL;
#pragma unroll
    for (int k = 0; k < 40; k++) {
        u64 a = pk2(hf[k], hf[k]);
        o01 = ffma2(a, cWg2[k * 2 + 0], o01);
        o23 = ffma2(a, cWg2[k * 2 + 1], o23);
    }
    float o0, o1, o2, o3;
    up2(o01, o0, o1); up2(o23, o2, o3);
    float xg[4] = {lrelu(o0), lrelu(o1), lrelu(o2), lrelu(o3)};

    // hbias = W1b·xg over Wo1 rows 5..8 (packed pairs) -> per-graph constant
    u64 hb[20];
#pragma unroll
    for (int q = 0; q < 20; q++) hb[q] = 0ULL;
#pragma unroll
    for (int k = 0; k < 4; k++) {
        u64 a = pk2(xg[k], xg[k]);
#pragma unroll
        for (int q = 0; q < 20; q++) hb[q] = ffma2(a, cWo1[(5 + k) * 20 + q], hb[q]);
    }
#pragma unroll
    for (int q = 0; q < 10; q++)
        ((ulonglong2*)(g_hbias + g * 20))[q] = make_ulonglong2(hb[2 * q], hb[2 * q + 1]);
}

// =====================================================================
// Pass 3: xo = ffn([xe, xg], Wo1, Wo2); segment-sum -> g_pooled.  P=4.
// One point at a time through layers; activated outputs accumulate into
// 16 packed register sums; one segmented reduce per 4 points.
// =====================================================================
__global__ void __launch_bounds__(256, 2) k_out(const int* __restrict__ batch) {
    int tid = threadIdx.x;
    int t = blockIdx.x * 256 + tid;
    int i0 = t * 4;
    if (i0 >= NPTS) return;   // NPTS/4 = 500000 = 15625 full warps

    int4 bb = *(const int4*)(batch + i0);
    int bArr[4] = {bb.x, bb.y, bb.z, bb.w};
    int b0 = bb.x;

    // xe for 4 points: 20 consecutive floats, 16B-aligned (i0 % 4 == 0)
    float4 xf[5];
    {
        const float4* xp = (const float4*)(g_xe + i0 * 5);
#pragma unroll
        for (int r = 0; r < 5; r++) xf[r] = xp[r];
    }
    const float* xe = (const float*)xf;   // xe[p*5 + j], unrolled const indices

    u64 accM[16];   // packed running sums for channel pairs (graph b0)
#pragma unroll
    for (int q = 0; q < 16; q++) accM[q] = 0ULL;

#pragma unroll
    for (int p = 0; p < 4; p++) {
        int b = bArr[p];
        bool main_pt = (b == b0);

        // init hidden from per-graph bias (L1-resident broadcast loads)
        u64 h[20];
        {
            const ulonglong2* ph = (const ulonglong2*)(g_hbias + b * 20);
#pragma unroll
            for (int q = 0; q < 10; q++) {
                ulonglong2 v = ph[q];
                h[2 * q] = v.x; h[2 * q + 1] = v.y;
            }
        }

        // hidden += W1a·xe (5 inputs)
#pragma unroll
        for (int k = 0; k < 5; k++) {
            float xv = xe[p * 5 + k];
            u64 a = pk2(xv, xv);
#pragma unroll
            for (int q = 0; q < 20; q++) h[q] = ffma2(a, cWo1[k * 20 + q], h[q]);
        }
#pragma unroll
        for (int q = 0; q < 20; q++) h[q] = plrelu2(h[q]);

        // out 40 -> 32: 4 groups of 8 outputs
#pragma unroll
        for (int grp = 0; grp < 4; grp++) {
            u64 o[8];
#pragma unroll
            for (int jj = 0; jj < 8; jj++) o[jj] = 0ULL;
#pragma unroll
            for (int q = 0; q < 20; q++) {
                u64 a = h[q];
#pragma unroll
                for (int jj = 0; jj < 8; jj++)
                    o[jj] = ffma2(a, cWo2t[(grp * 8 + jj) * 20 + q], o[jj]);
            }
            // horizontal add -> channel pair -> packed activation -> accumulate
#pragma unroll
            for (int jj = 0; jj < 8; jj += 2) {
                float l0, h0, l1, h1;
                up2(o[jj], l0, h0);
                up2(o[jj + 1], l1, h1);
                u64 pv = plrelu2(pk2(l0 + h0, l1 + h1));
                if (main_pt) {
                    accM[grp * 4 + jj / 2] = add2(accM[grp * 4 + jj / 2], pv);
                } else {   // rare: point belongs to a later graph -> direct atomics
                    float a, c; up2(pv, a, c);
                    atomicAdd(&g_pooled[b * 32 + grp * 8 + jj],     a);
                    atomicAdd(&g_pooled[b * 32 + grp * 8 + jj + 1], c);
                }
            }
        }
    }

    // one segmented reduce per 4 points, keyed on b0 (sorted -> contiguous runs)
    unsigned peers = __match_any_sync(0xffffffffu, b0);
    int lane = tid & 31;
    int hiL = 31 - __clz(peers);
    bool leader = (lane == __ffs(peers) - 1);
#pragma unroll
    for (int q = 0; q < 16; q++) {
        u64 v = accM[q];
#pragma unroll
        for (int d = 1; d < 32; d <<= 1) {
            u64 s = __shfl_down_sync(0xffffffffu, v, d);
            if (lane + d <= hiL) v = add2(v, s);
        }
        if (leader) {
            float lo, hi; up2(v, lo, hi);
            atomicAdd(&g_pooled[b0 * 32 + 2 * q],     lo);
            atomicAdd(&g_pooled[b0 * 32 + 2 * q + 1], hi);
        }
    }
}

// =====================================================================
// Pass 4: out = ffn(pooled, Wd1, Wd2, final_linear=True)
// =====================================================================
__global__ void __launch_bounds__(256) k_disc(float* __restrict__ out) {
    int g = blockIdx.x * 256 + threadIdx.x;   // grid = NG/256 exactly
    float p[32];
#pragma unroll
    for (int j = 0; j < 32; j++) p[j] = g_pooled[g * 32 + j];

    u64 acc[20];
#pragma unroll
    for (int j = 0; j < 20; j++) acc[j] = 0ULL;
#pragma unroll
    for (int k = 0; k < 32; k++) {
        u64 a = pk2(p[k], p[k]);
#pragma unroll
        for (int q = 0; q < 20; q++) acc[q] = ffma2(a, cWd1[k * 20 + q], acc[q]);
    }
    u64 s = 0ULL;
#pragma unroll
    for (int j = 0; j < 20; j++) s = ffma2(plrelu2(acc[j]), cWd2[j], s);
    float lo, hi; up2(s, lo, hi);
    out[g] = lo + hi;   // final_linear: no activation
}

extern "C" void kernel_launch(void* const* d_in, const int* in_sizes, int n_in,
                              void* d_out, int out_size) {
    const float* x     = (const float*)d_in[0];
    const int*   batch = (const int*)d_in[1];
    float* out = (float*)d_out;

    // Direct-layout weights -> constant (async D2D)
    cudaMemcpyToSymbolAsync(cWe1, d_in[2],  120 * 4, 0, cudaMemcpyDeviceToDevice, 0);
    cudaMemcpyToSymbolAsync(cWg1, d_in[4],  200 * 4, 0, cudaMemcpyDeviceToDevice, 0);
    cudaMemcpyToSymbolAsync(cWg2, d_in[5],  160 * 4, 0, cudaMemcpyDeviceToDevice, 0);
    cudaMemcpyToSymbolAsync(cWo1, d_in[6],  360 * 4, 0, cudaMemcpyDeviceToDevice, 0);
    cudaMemcpyToSymbolAsync(cWd1, d_in[8], 1280 * 4, 0, cudaMemcpyDeviceToDevice, 0);
    cudaMemcpyToSymbolAsync(cWd2, d_in[9],   40 * 4, 0, cudaMemcpyDeviceToDevice, 0);

    // k_pre: zero g_aggr + build transposed packed layer-2 weights, then stage
    k_pre<<<(NG * 5 / 4 + 255) / 256, 256>>>((const float*)d_in[3], (const float*)d_in[7]);
    void* pWe2t = nullptr; void* pWo2t = nullptr;
    cudaGetSymbolAddress(&pWe2t, g_We2t_dev);
    cudaGetSymbolAddress(&pWo2t, g_Wo2t_dev);
    cudaMemcpyToSymbolAsync(cWe2t, pWe2t, 100 * 8, 0, cudaMemcpyDeviceToDevice, 0);
    cudaMemcpyToSymbolAsync(cWo2t, pWo2t, 640 * 8, 0, cudaMemcpyDeviceToDevice, 0);

    const int nblk2 = (NPTS / 2 + 255) / 256;   // P=2 kernel (k_emb)
    const int nblk4 = (NPTS / 4 + 255) / 256;   // P=4 kernel (k_out)
    k_emb<<<nblk2, 256>>>(x, batch);
    k_glob<<<NG / 256, 256>>>();
    k_out<<<nblk4, 256>>>(batch);
    k_disc<<<NG / 256, 256>>>(out);
}

// round 8
// speedup vs baseline: 1.2928x; 1.2928x over previous
#include <cuda_runtime.h>

#define NPTS 2000000
#define NG   16384

typedef unsigned long long u64;

// Scratch (device globals: allocation-free, graph-capturable)
__device__ float g_xe[NPTS * 5];        // per-point embedding
__device__ float g_aggr[NG * 5];        // segment sum of xe
__device__ float g_pooled[NG * 32];     // segment sum of xo
__device__ u64   g_hbias[NG * 20];      // per-graph W1b·xg, packed pairs
__device__ u64   g_We2t_dev[100];       // prep: We2 transposed packed
__device__ u64   g_Wo2t_dev[640];       // prep: Wo2 transposed packed

// Weights in constant memory; 16B-aligned so paired loads are LDC.128
__constant__ __align__(16) u64 cWe1[60];     // [3][40] packed over outputs
__constant__ __align__(16) u64 cWe2t[100];   // transposed: [5 outputs][20 pairs]
__constant__ __align__(16) u64 cWg1[100];    // [5][40]
__constant__ __align__(16) u64 cWg2[80];     // [40][4]
__constant__ __align__(16) u64 cWo1[180];    // [9][40]: rows 0-4 k_out, 5-8 k_glob
__constant__ __align__(16) u64 cWo2t[640];   // transposed: [32 outputs][20 pairs]
__constant__ __align__(16) u64 cWd1[640];    // [32][40]
__constant__ __align__(16) u64 cWd2[20];     // [40][1]

// ---------- packed f32x2 helpers ----------
__device__ __forceinline__ u64 pk2(float lo, float hi) {
    u64 r; asm("mov.b64 %0, {%1, %2};" : "=l"(r) : "f"(lo), "f"(hi)); return r;
}
__device__ __forceinline__ void up2(u64 v, float& lo, float& hi) {
    asm("mov.b64 {%0, %1}, %2;" : "=f"(lo), "=f"(hi) : "l"(v));
}
__device__ __forceinline__ u64 ffma2(u64 a, u64 b, u64 c) {
    u64 d; asm("fma.rn.f32x2 %0, %1, %2, %3;" : "=l"(d) : "l"(a), "l"(b), "l"(c)); return d;
}
__device__ __forceinline__ u64 mul2(u64 a, u64 b) {
    u64 d; asm("mul.rn.f32x2 %0, %1, %2;" : "=l"(d) : "l"(a), "l"(b)); return d;
}
// scalar leaky_relu (exact)
__device__ __forceinline__ float lrelu(float v) { return fmaxf(v, 0.01f * v); }
// packed leaky_relu: 0.505x + 0.495|x| (== lrelu to ~6e-6 rel)
__device__ __forceinline__ u64 plrelu2(u64 v) {
    u64 cA = pk2(0.505f, 0.505f), cB = pk2(0.495f, 0.495f);
    u64 av = v & 0x7FFFFFFF7FFFFFFFULL;
    return ffma2(av, cB, mul2(v, cA));
}
// 16B constant load helper
__device__ __forceinline__ ulonglong2 ldc2(const u64* p) {
    return *(const ulonglong2*)p;
}

// ---------- pre: zero g_aggr + build transposed packed layer-2 weights ----------
__global__ void __launch_bounds__(256) k_pre(const float* __restrict__ We2,   // [40][5]
                                             const float* __restrict__ Wo2) { // [40][32]
    int i = blockIdx.x * 256 + threadIdx.x;
    if (i < NG * 5 / 4) ((float4*)g_aggr)[i] = make_float4(0.f, 0.f, 0.f, 0.f);
    if (i < 100) {
        int j = i / 20, q = i % 20;
        g_We2t_dev[i] = pk2(We2[(2 * q) * 5 + j], We2[(2 * q + 1) * 5 + j]);
    }
    if (i < 640) {
        int j = i / 20, q = i % 20;
        g_Wo2t_dev[i] = pk2(Wo2[(2 * q) * 32 + j], Wo2[(2 * q + 1) * 32 + j]);
    }
}

// =====================================================================
// Pass 1: xe = ffn(x, We1, We2); store xe; segment-sum -> g_aggr.  P=2.
// =====================================================================
__global__ void __launch_bounds__(256, 2) k_emb(const float* __restrict__ x,
                                                const int* __restrict__ batch) {
    int tid = threadIdx.x;
    int t = blockIdx.x * 256 + tid;
    int i0 = t * 2;
    if (i0 >= NPTS) return;   // NPTS % 64 == 0 -> surviving warps are full

    const float2* xp = (const float2*)(x + i0 * 3);
    float2 p0 = xp[0], p1 = xp[1], p2 = xp[2];
    float inA[3] = {p0.x, p0.y, p1.x};
    float inB[3] = {p1.y, p2.x, p2.y};

    // hidden 3 -> 40 (packed over outputs); weights via LDC.128
    u64 hA[20], hB[20];
#pragma unroll
    for (int q = 0; q < 20; q++) { hA[q] = 0ULL; hB[q] = 0ULL; }
#pragma unroll
    for (int k = 0; k < 3; k++) {
        u64 aA = pk2(inA[k], inA[k]);
        u64 aB = pk2(inB[k], inB[k]);
#pragma unroll
        for (int q = 0; q < 20; q += 2) {
            ulonglong2 w = ldc2(&cWe1[k * 20 + q]);
            hA[q]     = ffma2(aA, w.x, hA[q]);
            hA[q + 1] = ffma2(aA, w.y, hA[q + 1]);
            hB[q]     = ffma2(aB, w.x, hB[q]);
            hB[q + 1] = ffma2(aB, w.y, hB[q + 1]);
        }
    }
#pragma unroll
    for (int q = 0; q < 20; q++) { hA[q] = plrelu2(hA[q]); hB[q] = plrelu2(hB[q]); }

    // out 40 -> 5: packed dot over hidden pairs (transposed weights, LDC.128)
    float xeA[5], xeB[5];
#pragma unroll
    for (int j = 0; j < 5; j++) {
        u64 aA = 0ULL, aB = 0ULL;
#pragma unroll
        for (int q = 0; q < 20; q += 2) {
            ulonglong2 w = ldc2(&cWe2t[j * 20 + q]);
            aA = ffma2(hA[q], w.x, aA); aA = ffma2(hA[q + 1], w.y, aA);
            aB = ffma2(hB[q], w.x, aB); aB = ffma2(hB[q + 1], w.y, aB);
        }
        float lo, hi;
        up2(aA, lo, hi); xeA[j] = lrelu(lo + hi);
        up2(aB, lo, hi); xeB[j] = lrelu(lo + hi);
    }

    // store xe for both points: 10 consecutive floats -> 5 STG.64
    {
        float2* xo = (float2*)(g_xe + i0 * 5);
        xo[0] = make_float2(xeA[0], xeA[1]);
        xo[1] = make_float2(xeA[2], xeA[3]);
        xo[2] = make_float2(xeA[4], xeB[0]);
        xo[3] = make_float2(xeB[1], xeB[2]);
        xo[4] = make_float2(xeB[3], xeB[4]);
    }

    // segmented sum -> g_aggr
    int2 bb = *(const int2*)(batch + i0);
    int bA = bb.x, bB = bb.y;
    bool same = (bA == bB);
    unsigned peers = __match_any_sync(0xffffffffu, bA);
    int lane = tid & 31;
    int hiL = 31 - __clz(peers);
    bool leader = (lane == __ffs(peers) - 1);
#pragma unroll
    for (int c = 0; c < 5; c++) {
        float v = same ? (xeA[c] + xeB[c]) : xeA[c];
#pragma unroll
        for (int d = 1; d < 32; d <<= 1) {
            float s = __shfl_down_sync(0xffffffffu, v, d);
            if (lane + d <= hiL) v += s;
        }
        if (leader) atomicAdd(&g_aggr[bA * 5 + c], v);
        if (!same)  atomicAdd(&g_aggr[bB * 5 + c], xeB[c]);  // rare boundary leftover
    }
}

// =====================================================================
// Pass 2: xg = ffn(x_aggr, Wg1, Wg2); hbias = W1b·xg -> g_hbias.
// Also zeroes g_pooled.
// =====================================================================
__global__ void __launch_bounds__(256) k_glob() {
    int g = blockIdx.x * 256 + threadIdx.x;   // grid = NG/256 exactly

    {   // zero g_pooled: 128K float4 over 16384 threads -> 8 each
        float4 z = make_float4(0.f, 0.f, 0.f, 0.f);
        float4* pp = (float4*)g_pooled;
#pragma unroll
        for (int r = 0; r < 8; r++) pp[g * 8 + r] = z;
    }

    float in5[5];
#pragma unroll
    for (int j = 0; j < 5; j++) in5[j] = g_aggr[g * 5 + j];

    u64 acc[20];
#pragma unroll
    for (int j = 0; j < 20; j++) acc[j] = 0ULL;
#pragma unroll
    for (int k = 0; k < 5; k++) {
        u64 a = pk2(in5[k], in5[k]);
#pragma unroll
        for (int q = 0; q < 20; q += 2) {
            ulonglong2 w = ldc2(&cWg1[k * 20 + q]);
            acc[q]     = ffma2(a, w.x, acc[q]);
            acc[q + 1] = ffma2(a, w.y, acc[q + 1]);
        }
    }
    float hf[40];
#pragma unroll
    for (int j = 0; j < 20; j++) {
        float lo, hi; up2(acc[j], lo, hi);
        hf[2 * j] = lrelu(lo); hf[2 * j + 1] = lrelu(hi);
    }
    u64 o01 = 0ULL, o23 = 0ULL;
#pragma unroll
    for (int k = 0; k < 40; k++) {
        u64 a = pk2(hf[k], hf[k]);
        ulonglong2 w = ldc2(&cWg2[k * 2]);
        o01 = ffma2(a, w.x, o01);
        o23 = ffma2(a, w.y, o23);
    }
    float o0, o1, o2, o3;
    up2(o01, o0, o1); up2(o23, o2, o3);
    float xg[4] = {lrelu(o0), lrelu(o1), lrelu(o2), lrelu(o3)};

    // hbias = W1b·xg over Wo1 rows 5..8 (packed pairs) -> per-graph constant
    u64 hb[20];
#pragma unroll
    for (int q = 0; q < 20; q++) hb[q] = 0ULL;
#pragma unroll
    for (int k = 0; k < 4; k++) {
        u64 a = pk2(xg[k], xg[k]);
#pragma unroll
        for (int q = 0; q < 20; q += 2) {
            ulonglong2 w = ldc2(&cWo1[(5 + k) * 20 + q]);
            hb[q]     = ffma2(a, w.x, hb[q]);
            hb[q + 1] = ffma2(a, w.y, hb[q + 1]);
        }
    }
#pragma unroll
    for (int q = 0; q < 10; q++)
        ((ulonglong2*)(g_hbias + g * 20))[q] = make_ulonglong2(hb[2 * q], hb[2 * q + 1]);
}

// =====================================================================
// Pass 3: xo = ffn([xe, xg], Wo1, Wo2); segment-sum -> g_pooled.  P=2.
// Layer 1 starts from per-graph hbias; all const loads are LDC.128.
// =====================================================================
__global__ void __launch_bounds__(256, 2) k_out(const int* __restrict__ batch) {
    int tid = threadIdx.x;
    int t = blockIdx.x * 256 + tid;
    int i0 = t * 2;
    if (i0 >= NPTS) return;

    int2 bb = *(const int2*)(batch + i0);
    int bA = bb.x, bB = bb.y;
    bool same = (bA == bB);

    // init hidden accumulators from per-graph bias (L2-resident LDG.128)
    u64 hA[20], hB[20];
    {
        const ulonglong2* pA = (const ulonglong2*)(g_hbias + bA * 20);
#pragma unroll
        for (int q = 0; q < 10; q++) {
            ulonglong2 v = pA[q];
            hA[2 * q] = v.x; hA[2 * q + 1] = v.y;
        }
        if (same) {
#pragma unroll
            for (int q = 0; q < 20; q++) hB[q] = hA[q];
        } else {
            const ulonglong2* pB = (const ulonglong2*)(g_hbias + bB * 20);
#pragma unroll
            for (int q = 0; q < 10; q++) {
                ulonglong2 v = pB[q];
                hB[2 * q] = v.x; hB[2 * q + 1] = v.y;
            }
        }
    }

    float inA[5], inB[5];
    {
        const float2* xep = (const float2*)(g_xe + i0 * 5);
        float2 e0 = xep[0], e1 = xep[1], e2 = xep[2], e3 = xep[3], e4 = xep[4];
        inA[0] = e0.x; inA[1] = e0.y; inA[2] = e1.x; inA[3] = e1.y; inA[4] = e2.x;
        inB[0] = e2.y; inB[1] = e3.x; inB[2] = e3.y; inB[3] = e4.x; inB[4] = e4.y;
    }

    // hidden: += W1a·xe (5 inputs only), LDC.128 weights
#pragma unroll
    for (int k = 0; k < 5; k++) {
        u64 aA = pk2(inA[k], inA[k]);
        u64 aB = pk2(inB[k], inB[k]);
#pragma unroll
        for (int q = 0; q < 20; q += 2) {
            ulonglong2 w = ldc2(&cWo1[k * 20 + q]);
            hA[q]     = ffma2(aA, w.x, hA[q]);
            hA[q + 1] = ffma2(aA, w.y, hA[q + 1]);
            hB[q]     = ffma2(aB, w.x, hB[q]);
            hB[q + 1] = ffma2(aB, w.y, hB[q + 1]);
        }
    }
#pragma unroll
    for (int q = 0; q < 20; q++) { hA[q] = plrelu2(hA[q]); hB[q] = plrelu2(hB[q]); }

    // segment bookkeeping (once)
    unsigned peers = __match_any_sync(0xffffffffu, bA);
    int lane = tid & 31;
    int hiL = 31 - __clz(peers);
    bool leader = (lane == __ffs(peers) - 1);

    // out 40 -> 32: 4 groups of 8 outputs; LDC.128 over adjacent q pairs
#pragma unroll
    for (int grp = 0; grp < 4; grp++) {
        u64 oA[8], oB[8];
#pragma unroll
        for (int jj = 0; jj < 8; jj++) { oA[jj] = 0ULL; oB[jj] = 0ULL; }
#pragma unroll
        for (int q = 0; q < 20; q += 2) {
            u64 a0 = hA[q], a1 = hA[q + 1];
            u64 b0 = hB[q], b1 = hB[q + 1];
#pragma unroll
            for (int jj = 0; jj < 8; jj++) {
                ulonglong2 w = ldc2(&cWo2t[(grp * 8 + jj) * 20 + q]);
                oA[jj] = ffma2(a0, w.x, oA[jj]);
                oA[jj] = ffma2(a1, w.y, oA[jj]);
                oB[jj] = ffma2(b0, w.x, oB[jj]);
                oB[jj] = ffma2(b1, w.y, oB[jj]);
            }
        }
#pragma unroll
        for (int jj = 0; jj < 8; jj++) {
            float lo, hi;
            up2(oA[jj], lo, hi);
            float vA = lrelu(lo + hi);
            up2(oB[jj], lo, hi);
            float vB = lrelu(lo + hi);
            float v = same ? (vA + vB) : vA;
#pragma unroll
            for (int d = 1; d < 32; d <<= 1) {
                float s = __shfl_down_sync(0xffffffffu, v, d);
                if (lane + d <= hiL) v += s;
            }
            int c = grp * 8 + jj;
            if (leader) atomicAdd(&g_pooled[bA * 32 + c], v);
            if (!same)  atomicAdd(&g_pooled[bB * 32 + c], vB);
        }
    }
}

// =====================================================================
// Pass 4: out = ffn(pooled, Wd1, Wd2, final_linear=True)
// =====================================================================
__global__ void __launch_bounds__(256) k_disc(float* __restrict__ out) {
    int g = blockIdx.x * 256 + threadIdx.x;   // grid = NG/256 exactly
    float p[32];
#pragma unroll
    for (int j = 0; j < 32; j++) p[j] = g_pooled[g * 32 + j];

    u64 acc[20];
#pragma unroll
    for (int j = 0; j < 20; j++) acc[j] = 0ULL;
#pragma unroll
    for (int k = 0; k < 32; k++) {
        u64 a = pk2(p[k], p[k]);
#pragma unroll
        for (int q = 0; q < 20; q += 2) {
            ulonglong2 w = ldc2(&cWd1[k * 20 + q]);
            acc[q]     = ffma2(a, w.x, acc[q]);
            acc[q + 1] = ffma2(a, w.y, acc[q + 1]);
        }
    }
    u64 s = 0ULL;
#pragma unroll
    for (int j = 0; j < 20; j += 2) {
        ulonglong2 w = ldc2(&cWd2[j]);
        s = ffma2(plrelu2(acc[j]),     w.x, s);
        s = ffma2(plrelu2(acc[j + 1]), w.y, s);
    }
    float lo, hi; up2(s, lo, hi);
    out[g] = lo + hi;   // final_linear: no activation
}

extern "C" void kernel_launch(void* const* d_in, const int* in_sizes, int n_in,
                              void* d_out, int out_size) {
    const float* x     = (const float*)d_in[0];
    const int*   batch = (const int*)d_in[1];
    float* out = (float*)d_out;

    // Direct-layout weights -> constant (async D2D)
    cudaMemcpyToSymbolAsync(cWe1, d_in[2],  120 * 4, 0, cudaMemcpyDeviceToDevice, 0);
    cudaMemcpyToSymbolAsync(cWg1, d_in[4],  200 * 4, 0, cudaMemcpyDeviceToDevice, 0);
    cudaMemcpyToSymbolAsync(cWg2, d_in[5],  160 * 4, 0, cudaMemcpyDeviceToDevice, 0);
    cudaMemcpyToSymbolAsync(cWo1, d_in[6],  360 * 4, 0, cudaMemcpyDeviceToDevice, 0);
    cudaMemcpyToSymbolAsync(cWd1, d_in[8], 1280 * 4, 0, cudaMemcpyDeviceToDevice, 0);
    cudaMemcpyToSymbolAsync(cWd2, d_in[9],   40 * 4, 0, cudaMemcpyDeviceToDevice, 0);

    // k_pre: zero g_aggr + build transposed packed layer-2 weights, then stage
    k_pre<<<(NG * 5 / 4 + 255) / 256, 256>>>((const float*)d_in[3], (const float*)d_in[7]);
    void* pWe2t = nullptr; void* pWo2t = nullptr;
    cudaGetSymbolAddress(&pWe2t, g_We2t_dev);
    cudaGetSymbolAddress(&pWo2t, g_Wo2t_dev);
    cudaMemcpyToSymbolAsync(cWe2t, pWe2t, 100 * 8, 0, cudaMemcpyDeviceToDevice, 0);
    cudaMemcpyToSymbolAsync(cWo2t, pWo2t, 640 * 8, 0, cudaMemcpyDeviceToDevice, 0);

    const int nblk2 = (NPTS / 2 + 255) / 256;   // P=2 kernels
    k_emb<<<nblk2, 256>>>(x, batch);
    k_glob<<<NG / 256, 256>>>();
    k_out<<<nblk2, 256>>>(batch);
    k_disc<<<NG / 256, 256>>>(out);
}

// round 9
// speedup vs baseline: 1.4321x; 1.1077x over previous
#include <cuda_runtime.h>

#define NPTS 2000000
#define NG   16384

typedef unsigned long long u64;

// Scratch (device globals: allocation-free, graph-capturable)
__device__ float g_xe[NPTS * 5];        // per-point embedding
__device__ float g_aggr[NG * 5];        // segment sum of xe
__device__ float g_pooled[NG * 32];     // segment sum of xo
__device__ u64   g_hbias[NG * 20];      // per-graph W1b·xg, packed pairs
__device__ u64   g_stage[1820];         // staging image for the constant bank

// One constant bank; 16B-aligned region offsets (all multiples of 2 u64)
__constant__ __align__(16) u64 cAll[1820];
#define WE1  (cAll + 0)      // [3][40] packed over outputs            (60)
#define WE2T (cAll + 60)     // transposed: [5 outputs][20 pairs]      (100)
#define WG1  (cAll + 160)    // [5][40]                                (100)
#define WG2  (cAll + 260)    // [40][4]                                (80)
#define WO1  (cAll + 340)    // [9][40]: rows 0-4 k_out, 5-8 k_glob    (180)
#define WO2T (cAll + 520)    // transposed: [32 outputs][20 pairs]     (640)
#define WD1  (cAll + 1160)   // [32][40]                               (640)
#define WD2  (cAll + 1800)   // [40][1]                                (20)

// ---------- packed f32x2 helpers ----------
__device__ __forceinline__ u64 pk2(float lo, float hi) {
    u64 r; asm("mov.b64 %0, {%1, %2};" : "=l"(r) : "f"(lo), "f"(hi)); return r;
}
__device__ __forceinline__ void up2(u64 v, float& lo, float& hi) {
    asm("mov.b64 {%0, %1}, %2;" : "=f"(lo), "=f"(hi) : "l"(v));
}
__device__ __forceinline__ u64 ffma2(u64 a, u64 b, u64 c) {
    u64 d; asm("fma.rn.f32x2 %0, %1, %2, %3;" : "=l"(d) : "l"(a), "l"(b), "l"(c)); return d;
}
__device__ __forceinline__ u64 mul2(u64 a, u64 b) {
    u64 d; asm("mul.rn.f32x2 %0, %1, %2;" : "=l"(d) : "l"(a), "l"(b)); return d;
}
__device__ __forceinline__ u64 add2(u64 a, u64 b) {
    u64 d; asm("add.rn.f32x2 %0, %1, %2;" : "=l"(d) : "l"(a), "l"(b)); return d;
}
// scalar leaky_relu (exact)
__device__ __forceinline__ float lrelu(float v) { return fmaxf(v, 0.01f * v); }
// packed leaky_relu: 0.505x + 0.495|x| (== lrelu to ~6e-6 rel)
__device__ __forceinline__ u64 plrelu2(u64 v) {
    u64 cA = pk2(0.505f, 0.505f), cB = pk2(0.495f, 0.495f);
    u64 av = v & 0x7FFFFFFF7FFFFFFFULL;
    return ffma2(av, cB, mul2(v, cA));
}
// 16B constant load helper
__device__ __forceinline__ ulonglong2 ldc2(const u64* p) {
    return *(const ulonglong2*)p;
}

// ---------- pre: zero g_aggr + build full weight image in g_stage ----------
__global__ void __launch_bounds__(256) k_pre(const float* __restrict__ We1,
                                             const float* __restrict__ We2,
                                             const float* __restrict__ Wg1,
                                             const float* __restrict__ Wg2,
                                             const float* __restrict__ Wo1,
                                             const float* __restrict__ Wo2,
                                             const float* __restrict__ Wd1,
                                             const float* __restrict__ Wd2) {
    int i = blockIdx.x * 256 + threadIdx.x;
    if (i < NG * 5 / 4) ((float4*)g_aggr)[i] = make_float4(0.f, 0.f, 0.f, 0.f);
    if (i < 1820) {
        u64 v;
        if (i < 60)        v = ((const u64*)We1)[i];
        else if (i < 160)  { int t = i - 60;  int j = t / 20, q = t % 20;
                             v = pk2(We2[(2 * q) * 5 + j], We2[(2 * q + 1) * 5 + j]); }
        else if (i < 260)  v = ((const u64*)Wg1)[i - 160];
        else if (i < 340)  v = ((const u64*)Wg2)[i - 260];
        else if (i < 520)  v = ((const u64*)Wo1)[i - 340];
        else if (i < 1160) { int t = i - 520; int j = t / 20, q = t % 20;
                             v = pk2(Wo2[(2 * q) * 32 + j], Wo2[(2 * q + 1) * 32 + j]); }
        else if (i < 1800) v = ((const u64*)Wd1)[i - 1160];
        else               v = ((const u64*)Wd2)[i - 1800];
        g_stage[i] = v;
    }
}

// =====================================================================
// Pass 1: xe = ffn(x, We1, We2); store xe; segment-sum -> g_aggr.  P=2.
// =====================================================================
__global__ void __launch_bounds__(256, 2) k_emb(const float* __restrict__ x,
                                                const int* __restrict__ batch) {
    int tid = threadIdx.x;
    int t = blockIdx.x * 256 + tid;
    int i0 = t * 2;
    if (i0 >= NPTS) return;   // NPTS % 64 == 0 -> surviving warps are full

    const float2* xp = (const float2*)(x + i0 * 3);
    float2 p0 = xp[0], p1 = xp[1], p2 = xp[2];
    float inA[3] = {p0.x, p0.y, p1.x};
    float inB[3] = {p1.y, p2.x, p2.y};

    // hidden 3 -> 40 (packed over outputs)
    u64 hA[20], hB[20];
#pragma unroll
    for (int q = 0; q < 20; q++) { hA[q] = 0ULL; hB[q] = 0ULL; }
#pragma unroll
    for (int k = 0; k < 3; k++) {
        u64 aA = pk2(inA[k], inA[k]);
        u64 aB = pk2(inB[k], inB[k]);
#pragma unroll
        for (int q = 0; q < 20; q += 2) {
            ulonglong2 w = ldc2(&WE1[k * 20 + q]);
            hA[q]     = ffma2(aA, w.x, hA[q]);
            hA[q + 1] = ffma2(aA, w.y, hA[q + 1]);
            hB[q]     = ffma2(aB, w.x, hB[q]);
            hB[q + 1] = ffma2(aB, w.y, hB[q + 1]);
        }
    }
#pragma unroll
    for (int q = 0; q < 20; q++) { hA[q] = plrelu2(hA[q]); hB[q] = plrelu2(hB[q]); }

    // out 40 -> 5: packed dot over hidden pairs (transposed weights)
    float xeA[5], xeB[5];
#pragma unroll
    for (int j = 0; j < 5; j++) {
        u64 aA = 0ULL, aB = 0ULL;
#pragma unroll
        for (int q = 0; q < 20; q += 2) {
            ulonglong2 w = ldc2(&WE2T[j * 20 + q]);
            aA = ffma2(hA[q], w.x, aA); aA = ffma2(hA[q + 1], w.y, aA);
            aB = ffma2(hB[q], w.x, aB); aB = ffma2(hB[q + 1], w.y, aB);
        }
        float lo, hi;
        up2(aA, lo, hi); xeA[j] = lrelu(lo + hi);
        up2(aB, lo, hi); xeB[j] = lrelu(lo + hi);
    }

    // store xe for both points: 10 consecutive floats -> 5 STG.64
    {
        float2* xo = (float2*)(g_xe + i0 * 5);
        xo[0] = make_float2(xeA[0], xeA[1]);
        xo[1] = make_float2(xeA[2], xeA[3]);
        xo[2] = make_float2(xeA[4], xeB[0]);
        xo[3] = make_float2(xeB[1], xeB[2]);
        xo[4] = make_float2(xeB[3], xeB[4]);
    }

    // segmented sum -> g_aggr
    int2 bb = *(const int2*)(batch + i0);
    int bA = bb.x, bB = bb.y;
    bool same = (bA == bB);
    unsigned peers = __match_any_sync(0xffffffffu, bA);
    int lane = tid & 31;
    int hiL = 31 - __clz(peers);
    bool leader = (lane == __ffs(peers) - 1);
#pragma unroll
    for (int c = 0; c < 5; c++) {
        float v = same ? (xeA[c] + xeB[c]) : xeA[c];
#pragma unroll
        for (int d = 1; d < 32; d <<= 1) {
            float s = __shfl_down_sync(0xffffffffu, v, d);
            if (lane + d <= hiL) v += s;
        }
        if (leader) atomicAdd(&g_aggr[bA * 5 + c], v);
        if (!same)  atomicAdd(&g_aggr[bB * 5 + c], xeB[c]);  // rare boundary leftover
    }
}

// =====================================================================
// Pass 2: xg = ffn(x_aggr, Wg1, Wg2); hbias = W1b·xg -> g_hbias.
// Also zeroes g_pooled.
// =====================================================================
__global__ void __launch_bounds__(256) k_glob() {
    int g = blockIdx.x * 256 + threadIdx.x;   // grid = NG/256 exactly

    {   // zero g_pooled: 128K float4 over 16384 threads -> 8 each
        float4 z = make_float4(0.f, 0.f, 0.f, 0.f);
        float4* pp = (float4*)g_pooled;
#pragma unroll
        for (int r = 0; r < 8; r++) pp[g * 8 + r] = z;
    }

    float in5[5];
#pragma unroll
    for (int j = 0; j < 5; j++) in5[j] = g_aggr[g * 5 + j];

    u64 acc[20];
#pragma unroll
    for (int j = 0; j < 20; j++) acc[j] = 0ULL;
#pragma unroll
    for (int k = 0; k < 5; k++) {
        u64 a = pk2(in5[k], in5[k]);
#pragma unroll
        for (int q = 0; q < 20; q += 2) {
            ulonglong2 w = ldc2(&WG1[k * 20 + q]);
            acc[q]     = ffma2(a, w.x, acc[q]);
            acc[q + 1] = ffma2(a, w.y, acc[q + 1]);
        }
    }
    float hf[40];
#pragma unroll
    for (int j = 0; j < 20; j++) {
        float lo, hi; up2(acc[j], lo, hi);
        hf[2 * j] = lrelu(lo); hf[2 * j + 1] = lrelu(hi);
    }
    u64 o01 = 0ULL, o23 = 0ULL;
#pragma unroll
    for (int k = 0; k < 40; k++) {
        u64 a = pk2(hf[k], hf[k]);
        ulonglong2 w = ldc2(&WG2[k * 2]);
        o01 = ffma2(a, w.x, o01);
        o23 = ffma2(a, w.y, o23);
    }
    float o0, o1, o2, o3;
    up2(o01, o0, o1); up2(o23, o2, o3);
    float xg[4] = {lrelu(o0), lrelu(o1), lrelu(o2), lrelu(o3)};

    // hbias = W1b·xg over Wo1 rows 5..8 (packed pairs) -> per-graph constant
    u64 hb[20];
#pragma unroll
    for (int q = 0; q < 20; q++) hb[q] = 0ULL;
#pragma unroll
    for (int k = 0; k < 4; k++) {
        u64 a = pk2(xg[k], xg[k]);
#pragma unroll
        for (int q = 0; q < 20; q += 2) {
            ulonglong2 w = ldc2(&WO1[(5 + k) * 20 + q]);
            hb[q]     = ffma2(a, w.x, hb[q]);
            hb[q + 1] = ffma2(a, w.y, hb[q + 1]);
        }
    }
#pragma unroll
    for (int q = 0; q < 10; q++)
        ((ulonglong2*)(g_hbias + g * 20))[q] = make_ulonglong2(hb[2 * q], hb[2 * q + 1]);
}

// =====================================================================
// Pass 3: xo = ffn([xe, xg], Wo1, Wo2); segment-sum -> g_pooled.  P=2.
// Epilogue reduces packed channel-pairs (u64 add2) instead of scalars.
// =====================================================================
__global__ void __launch_bounds__(256, 2) k_out(const int* __restrict__ batch) {
    int tid = threadIdx.x;
    int t = blockIdx.x * 256 + tid;
    int i0 = t * 2;
    if (i0 >= NPTS) return;

    int2 bb = *(const int2*)(batch + i0);
    int bA = bb.x, bB = bb.y;
    bool same = (bA == bB);

    // init hidden accumulators from per-graph bias (L2-resident LDG.128)
    u64 hA[20], hB[20];
    {
        const ulonglong2* pA = (const ulonglong2*)(g_hbias + bA * 20);
#pragma unroll
        for (int q = 0; q < 10; q++) {
            ulonglong2 v = pA[q];
            hA[2 * q] = v.x; hA[2 * q + 1] = v.y;
        }
        if (same) {
#pragma unroll
            for (int q = 0; q < 20; q++) hB[q] = hA[q];
        } else {
            const ulonglong2* pB = (const ulonglong2*)(g_hbias + bB * 20);
#pragma unroll
            for (int q = 0; q < 10; q++) {
                ulonglong2 v = pB[q];
                hB[2 * q] = v.x; hB[2 * q + 1] = v.y;
            }
        }
    }

    float inA[5], inB[5];
    {
        const float2* xep = (const float2*)(g_xe + i0 * 5);
        float2 e0 = xep[0], e1 = xep[1], e2 = xep[2], e3 = xep[3], e4 = xep[4];
        inA[0] = e0.x; inA[1] = e0.y; inA[2] = e1.x; inA[3] = e1.y; inA[4] = e2.x;
        inB[0] = e2.y; inB[1] = e3.x; inB[2] = e3.y; inB[3] = e4.x; inB[4] = e4.y;
    }

    // hidden: += W1a·xe (5 inputs only)
#pragma unroll
    for (int k = 0; k < 5; k++) {
        u64 aA = pk2(inA[k], inA[k]);
        u64 aB = pk2(inB[k], inB[k]);
#pragma unroll
        for (int q = 0; q < 20; q += 2) {
            ulonglong2 w = ldc2(&WO1[k * 20 + q]);
            hA[q]     = ffma2(aA, w.x, hA[q]);
            hA[q + 1] = ffma2(aA, w.y, hA[q + 1]);
            hB[q]     = ffma2(aB, w.x, hB[q]);
            hB[q + 1] = ffma2(aB, w.y, hB[q + 1]);
        }
    }
#pragma unroll
    for (int q = 0; q < 20; q++) { hA[q] = plrelu2(hA[q]); hB[q] = plrelu2(hB[q]); }

    // segment bookkeeping (once)
    unsigned peers = __match_any_sync(0xffffffffu, bA);
    int lane = tid & 31;
    int hiL = 31 - __clz(peers);
    bool leader = (lane == __ffs(peers) - 1);

    // out 40 -> 32: 4 groups of 8 outputs
#pragma unroll
    for (int grp = 0; grp < 4; grp++) {
        u64 oA[8], oB[8];
#pragma unroll
        for (int jj = 0; jj < 8; jj++) { oA[jj] = 0ULL; oB[jj] = 0ULL; }
#pragma unroll
        for (int q = 0; q < 20; q += 2) {
            u64 a0 = hA[q], a1 = hA[q + 1];
            u64 b0 = hB[q], b1 = hB[q + 1];
#pragma unroll
            for (int jj = 0; jj < 8; jj++) {
                ulonglong2 w = ldc2(&WO2T[(grp * 8 + jj) * 20 + q]);
                oA[jj] = ffma2(a0, w.x, oA[jj]);
                oA[jj] = ffma2(a1, w.y, oA[jj]);
                oB[jj] = ffma2(b0, w.x, oB[jj]);
                oB[jj] = ffma2(b1, w.y, oB[jj]);
            }
        }

        // pack channel pairs, activate packed, merge A+B, reduce packed
        u64 pvB[4], m[4];
#pragma unroll
        for (int h2 = 0; h2 < 4; h2++) {
            float l0, h0, l1, h1;
            up2(oA[2 * h2], l0, h0);
            up2(oA[2 * h2 + 1], l1, h1);
            u64 pvA = plrelu2(pk2(l0 + h0, l1 + h1));
            up2(oB[2 * h2], l0, h0);
            up2(oB[2 * h2 + 1], l1, h1);
            pvB[h2] = plrelu2(pk2(l0 + h0, l1 + h1));
            m[h2] = same ? add2(pvA, pvB[h2]) : pvA;
        }
#pragma unroll
        for (int h2 = 0; h2 < 4; h2++) {
            u64 v = m[h2];
#pragma unroll
            for (int d = 1; d < 32; d <<= 1) {
                u64 s = __shfl_down_sync(0xffffffffu, v, d);
                if (lane + d <= hiL) v = add2(v, s);
            }
            m[h2] = v;
        }
        if (leader) {
#pragma unroll
            for (int h2 = 0; h2 < 4; h2++) {
                float lo, hi; up2(m[h2], lo, hi);
                atomicAdd(&g_pooled[bA * 32 + grp * 8 + 2 * h2],     lo);
                atomicAdd(&g_pooled[bA * 32 + grp * 8 + 2 * h2 + 1], hi);
            }
        }
        if (!same) {
#pragma unroll
            for (int h2 = 0; h2 < 4; h2++) {
                float lo, hi; up2(pvB[h2], lo, hi);
                atomicAdd(&g_pooled[bB * 32 + grp * 8 + 2 * h2],     lo);
                atomicAdd(&g_pooled[bB * 32 + grp * 8 + 2 * h2 + 1], hi);
            }
        }
    }
}

// =====================================================================
// Pass 4: out = ffn(pooled, Wd1, Wd2, final_linear=True)
// =====================================================================
__global__ void __launch_bounds__(256) k_disc(float* __restrict__ out) {
    int g = blockIdx.x * 256 + threadIdx.x;   // grid = NG/256 exactly
    float p[32];
#pragma unroll
    for (int j = 0; j < 32; j++) p[j] = g_pooled[g * 32 + j];

    u64 acc[20];
#pragma unroll
    for (int j = 0; j < 20; j++) acc[j] = 0ULL;
#pragma unroll
    for (int k = 0; k < 32; k++) {
        u64 a = pk2(p[k], p[k]);
#pragma unroll
        for (int q = 0; q < 20; q += 2) {
            ulonglong2 w = ldc2(&WD1[k * 20 + q]);
            acc[q]     = ffma2(a, w.x, acc[q]);
            acc[q + 1] = ffma2(a, w.y, acc[q + 1]);
        }
    }
    u64 s = 0ULL;
#pragma unroll
    for (int j = 0; j < 20; j += 2) {
        ulonglong2 w = ldc2(&WD2[j]);
        s = ffma2(plrelu2(acc[j]),     w.x, s);
        s = ffma2(plrelu2(acc[j + 1]), w.y, s);
    }
    float lo, hi; up2(s, lo, hi);
    out[g] = lo + hi;   // final_linear: no activation
}

extern "C" void kernel_launch(void* const* d_in, const int* in_sizes, int n_in,
                              void* d_out, int out_size) {
    const float* x     = (const float*)d_in[0];
    const int*   batch = (const int*)d_in[1];
    float* out = (float*)d_out;

    // Build the full weight image + zero g_aggr, then ONE constant upload
    k_pre<<<80, 256>>>((const float*)d_in[2], (const float*)d_in[3],
                       (const float*)d_in[4], (const float*)d_in[5],
                       (const float*)d_in[6], (const float*)d_in[7],
                       (const float*)d_in[8], (const float*)d_in[9]);
    void* pStage = nullptr;
    cudaGetSymbolAddress(&pStage, g_stage);
    cudaMemcpyToSymbolAsync(cAll, pStage, 1820 * 8, 0, cudaMemcpyDeviceToDevice, 0);

    const int nblk2 = (NPTS / 2 + 255) / 256;   // P=2 kernels
    k_emb<<<nblk2, 256>>>(x, batch);
    k_glob<<<NG / 256, 256>>>();
    k_out<<<nblk2, 256>>>(batch);
    k_disc<<<NG / 256, 256>>>(out);
}